// round 15
// baseline (speedup 1.0000x reference)
#include <cuda_runtime.h>
#include <cuda_bf16.h>
#include <cstdint>

#define N_NODES 100000
#define N_EDGES 1600000
#define D 64
#define H 128
#define CAP 64

#define STRA 72      // bf16 row stride for A/H tiles (36 words, conflict-free)

typedef uint32_t u32;

// ---- device scratch (no allocation allowed) ----
__device__ float g_agg[N_NODES * D];
__device__ int g_cnt[N_NODES];
__device__ int g_bucket[(size_t)N_NODES * CAP];
// fragment-ordered weights: [kt][nt][word][lane], coalesced 128B per frag word
__device__ __align__(16) u32 g_w1f_hi[4 * 16 * 2 * 32];
__device__ __align__(16) u32 g_w1f_lo[4 * 16 * 2 * 32];
__device__ __align__(16) u32 g_w2f_hi[8 * 8 * 2 * 32];
__device__ __align__(16) u32 g_w2f_lo[8 * 8 * 2 * 32];

// ---- helpers ----
__device__ __forceinline__ void mma16816(float* c, u32 a0, u32 a1, u32 a2, u32 a3,
                                         u32 b0, u32 b1) {
    asm volatile(
        "mma.sync.aligned.m16n8k16.row.col.f32.bf16.bf16.f32 "
        "{%0,%1,%2,%3}, {%4,%5,%6,%7}, {%8,%9}, {%0,%1,%2,%3};"
        : "+f"(c[0]), "+f"(c[1]), "+f"(c[2]), "+f"(c[3])
        : "r"(a0), "r"(a1), "r"(a2), "r"(a3), "r"(b0), "r"(b1));
}

__device__ __forceinline__ void split2(float x0, float x1, u32& hi, u32& lo) {
    __nv_bfloat16 h0 = __float2bfloat16_rn(x0);
    __nv_bfloat16 h1 = __float2bfloat16_rn(x1);
    float r0 = x0 - __bfloat162float(h0);
    float r1 = x1 - __bfloat162float(h1);
    __nv_bfloat16 l0 = __float2bfloat16_rn(r0);
    __nv_bfloat16 l1 = __float2bfloat16_rn(r1);
    __nv_bfloat162 hp; hp.x = h0; hp.y = h1;
    __nv_bfloat162 lp; lp.x = l0; lp.y = l1;
    hi = *reinterpret_cast<u32*>(&hp);
    lo = *reinterpret_cast<u32*>(&lp);
}

__device__ __forceinline__ u32 packbf(float a, float b) {
    __nv_bfloat162 p;
    p.x = __float2bfloat16_rn(a);
    p.y = __float2bfloat16_rn(b);
    return *reinterpret_cast<u32*>(&p);
}

// ===========================================================================
// Fill: 4 edges per thread
// ===========================================================================
__global__ void fill_kernel(const int* __restrict__ edge_index) {
    int gid = blockIdx.x * blockDim.x + threadIdx.x;
    if (gid >= N_EDGES / 4) return;
    int4 s4 = reinterpret_cast<const int4*>(edge_index)[gid];
    int4 d4 = reinterpret_cast<const int4*>(edge_index + N_EDGES)[gid];
    int p;
    p = atomicAdd(&g_cnt[d4.x], 1);
    if (p < CAP) g_bucket[(size_t)d4.x * CAP + p] = s4.x;
    p = atomicAdd(&g_cnt[d4.y], 1);
    if (p < CAP) g_bucket[(size_t)d4.y * CAP + p] = s4.y;
    p = atomicAdd(&g_cnt[d4.z], 1);
    if (p < CAP) g_bucket[(size_t)d4.z * CAP + p] = s4.z;
    p = atomicAdd(&g_cnt[d4.w], 1);
    if (p < CAP) g_bucket[(size_t)d4.w * CAP + p] = s4.w;
}

// ===========================================================================
// Gather: half-warp per node (unchanged from R14)
// ===========================================================================
__global__ void __launch_bounds__(256) gather_kernel(const float4* __restrict__ x) {
    int hw = (blockIdx.x * 256 + threadIdx.x) >> 4;
    if (hw >= N_NODES) return;
    int q = threadIdx.x & 15;

    const int* bkt = g_bucket + (size_t)hw * CAP;
    int deg = g_cnt[hw];
    if (deg > CAP) deg = CAP;

    float4 acc = __ldg(&x[(size_t)hw * 16 + q]);
    float4 acc2 = make_float4(0.f, 0.f, 0.f, 0.f);

    int i = 0;
    for (; i + 1 < deg; i += 2) {
        int s0 = __ldg(&bkt[i]);
        int s1 = __ldg(&bkt[i + 1]);
        float4 v0 = __ldg(&x[(size_t)s0 * 16 + q]);
        float4 v1 = __ldg(&x[(size_t)s1 * 16 + q]);
        acc.x += v0.x;  acc.y += v0.y;  acc.z += v0.z;  acc.w += v0.w;
        acc2.x += v1.x; acc2.y += v1.y; acc2.z += v1.z; acc2.w += v1.w;
    }
    if (i < deg) {
        int s0 = __ldg(&bkt[i]);
        float4 v0 = __ldg(&x[(size_t)s0 * 16 + q]);
        acc.x += v0.x; acc.y += v0.y; acc.z += v0.z; acc.w += v0.w;
    }
    acc.x += acc2.x; acc.y += acc2.y; acc.z += acc2.z; acc.w += acc2.w;

    reinterpret_cast<float4*>(g_agg)[(size_t)hw * 16 + q] = acc;
}

// ===========================================================================
// One-time weight split into fragment-ordered global arrays.
// W1 frag word: lane=(i&31), word=(i>>5)&1, nt=(i>>6)&15, kt=(i>>10)
//   j = nt*8 + (lane>>2); k = kt*16 + (lane&3)*2 + word*8
//   u32 = bf16(W1T[j][k]) | bf16(W1T[j][k+1])<<16,  W1T[j][k] = W1[k*H+j]
// W2 frag word: lane, word, nt=(i>>6)&7, kt=(i>>9)
//   d = nt*8 + (lane>>2); j = kt*16 + (lane&3)*2 + word*8
//   u32 = bf16(W2T[d][j]) | bf16(W2T[d][j+1])<<16,  W2T[d][j] = W2[j*D+d]
// ===========================================================================
__global__ void split_w_kernel(const float* __restrict__ W1,
                               const float* __restrict__ W2) {
    int i = blockIdx.x * blockDim.x + threadIdx.x;
    if (i < 4096) {                                   // W1 frags
        int lane = i & 31, word = (i >> 5) & 1;
        int nt = (i >> 6) & 15, kt = i >> 10;
        int j = nt * 8 + (lane >> 2);
        int k = kt * 16 + (lane & 3) * 2 + word * 8;
        float w0 = W1[k * H + j];
        float w1 = W1[(k + 1) * H + j];
        u32 h0, l0;
        split2(w0, w1, h0, l0);
        g_w1f_hi[i] = h0;
        g_w1f_lo[i] = l0;
    } else if (i < 8192) {                            // W2 frags
        int p = i - 4096;
        int lane = p & 31, word = (p >> 5) & 1;
        int nt = (p >> 6) & 7, kt = p >> 9;
        int d = nt * 8 + (lane >> 2);
        int j = kt * 16 + (lane & 3) * 2 + word * 8;
        float w0 = W2[j * D + d];
        float w1 = W2[(j + 1) * D + d];
        u32 h0, l0;
        split2(w0, w1, h0, l0);
        g_w2f_hi[p] = h0;
        g_w2f_lo[p] = l0;
    }
}

// ===========================================================================
// Warp-autonomous mma.sync MLP. 128 nodes/block, 256 threads, NO barriers.
// Warp w owns rows 16w..16w+15 end-to-end.
// SMEM: [0,36864) A hi/lo (overlaid by H_B = j 64..127 after pass 1)
//       [36864,73728) H_A = j 0..63 hi/lo
// ===========================================================================
#define OFF_AHI   0
#define OFF_ALO   18432
#define OFF_HAHI  36864
#define OFF_HALO  55296
#define SMEM_SZ   73728

__global__ void __launch_bounds__(256, 3) mlp_mma_kernel(
    const float* __restrict__ b1, const float* __restrict__ b2,
    float* __restrict__ out)
{
    extern __shared__ unsigned char sm[];
    __nv_bfloat16* Ahi  = (__nv_bfloat16*)(sm + OFF_AHI);
    __nv_bfloat16* Alo  = (__nv_bfloat16*)(sm + OFF_ALO);
    __nv_bfloat16* HAhi = (__nv_bfloat16*)(sm + OFF_HAHI);
    __nv_bfloat16* HAlo = (__nv_bfloat16*)(sm + OFF_HALO);
    __nv_bfloat16* HBhi = Ahi;     // overlay after A consumed (warp-local)
    __nv_bfloat16* HBlo = Alo;

    const int t    = threadIdx.x;
    const int w    = t >> 5;
    const int lane = t & 31;
    const int g    = lane >> 2;
    const int tq   = (lane & 3) * 2;
    const int n0   = blockIdx.x * 128;

    // ---- stage A (warp-local rows 16w..16w+15) ----
    {
        int n = t >> 1, half = t & 1;
        int node = n0 + n;
        const float4* ap = reinterpret_cast<const float4*>(g_agg)
                           + (size_t)node * 16 + half * 8;
        #pragma unroll
        for (int q = 0; q < 8; q++) {
            float4 v = (node < N_NODES) ? __ldg(&ap[q])
                                        : make_float4(0.f, 0.f, 0.f, 0.f);
            int k = half * 32 + 4 * q;
            u32 h0, l0, h1, l1;
            split2(v.x, v.y, h0, l0);
            split2(v.z, v.w, h1, l1);
            *(u32*)(Ahi + n * STRA + k)     = h0;
            *(u32*)(Ahi + n * STRA + k + 2) = h1;
            *(u32*)(Alo + n * STRA + k)     = l0;
            *(u32*)(Alo + n * STRA + k + 2) = l1;
        }
    }
    __syncwarp();

    const int r0 = 16 * w + g;
    const int r1 = r0 + 8;

    // ---- layer 1: two j-passes (pass p covers j in [64p, 64p+64)) ----
    #pragma unroll
    for (int p = 0; p < 2; p++) {
        float acc[8][4];
        #pragma unroll
        for (int nt = 0; nt < 8; nt++)
            #pragma unroll
            for (int i = 0; i < 4; i++) acc[nt][i] = 0.f;

        const __nv_bfloat16* A0h = Ahi + r0 * STRA;
        const __nv_bfloat16* A1h = Ahi + r1 * STRA;
        const __nv_bfloat16* A0l = Alo + r0 * STRA;
        const __nv_bfloat16* A1l = Alo + r1 * STRA;
        #pragma unroll
        for (int kt = 0; kt < 4; kt++) {
            int k0 = kt * 16;
            u32 ah0 = *(const u32*)(A0h + k0 + tq);
            u32 ah1 = *(const u32*)(A1h + k0 + tq);
            u32 ah2 = *(const u32*)(A0h + k0 + tq + 8);
            u32 ah3 = *(const u32*)(A1h + k0 + tq + 8);
            u32 al0 = *(const u32*)(A0l + k0 + tq);
            u32 al1 = *(const u32*)(A1l + k0 + tq);
            u32 al2 = *(const u32*)(A0l + k0 + tq + 8);
            u32 al3 = *(const u32*)(A1l + k0 + tq + 8);
            #pragma unroll
            for (int nt2 = 0; nt2 < 8; nt2++) {
                int nt = p * 8 + nt2;
                int fi = ((kt * 16 + nt) * 2) * 32 + lane;
                u32 bh0 = __ldg(&g_w1f_hi[fi]);
                u32 bh1 = __ldg(&g_w1f_hi[fi + 32]);
                u32 bl0 = __ldg(&g_w1f_lo[fi]);
                u32 bl1 = __ldg(&g_w1f_lo[fi + 32]);
                mma16816(acc[nt2], ah0, ah1, ah2, ah3, bh0, bh1);
                mma16816(acc[nt2], ah0, ah1, ah2, ah3, bl0, bl1);
                mma16816(acc[nt2], al0, al1, al2, al3, bh0, bh1);
            }
        }

        // epilogue: relu + bias, split, write H half (warp-local rows).
        // Pass 1 overlays A — safe: this warp has finished reading A.
        __nv_bfloat16* Dhi = p ? HBhi : HAhi;
        __nv_bfloat16* Dlo = p ? HBlo : HAlo;
        __syncwarp();
        #pragma unroll
        for (int nt2 = 0; nt2 < 8; nt2++) {
            int j0 = p * 64 + 8 * nt2 + tq;     // global j
            int c0 = 8 * nt2 + tq;              // local col in half-buffer
            float bA = __ldg(&b1[j0]);
            float bB = __ldg(&b1[j0 + 1]);
            float h00 = fmaxf(acc[nt2][0] + bA, 0.f);
            float h01 = fmaxf(acc[nt2][1] + bB, 0.f);
            float h10 = fmaxf(acc[nt2][2] + bA, 0.f);
            float h11 = fmaxf(acc[nt2][3] + bB, 0.f);
            u32 hi, lo;
            split2(h00, h01, hi, lo);
            *(u32*)(Dhi + r0 * STRA + c0) = hi;
            *(u32*)(Dlo + r0 * STRA + c0) = lo;
            split2(h10, h11, hi, lo);
            *(u32*)(Dhi + r1 * STRA + c0) = hi;
            *(u32*)(Dlo + r1 * STRA + c0) = lo;
        }
        __syncwarp();
    }

    // ---- layer 2: K=128 (kt<4 from H_A, kt>=4 from H_B) ----
    float acc2[8][4];
    #pragma unroll
    for (int nt = 0; nt < 8; nt++)
        #pragma unroll
        for (int i = 0; i < 4; i++) acc2[nt][i] = 0.f;

    #pragma unroll
    for (int kt = 0; kt < 8; kt++) {
        const __nv_bfloat16* Shi = (kt < 4) ? HAhi : HBhi;
        const __nv_bfloat16* Slo = (kt < 4) ? HAlo : HBlo;
        int k0 = (kt & 3) * 16;
        u32 ah0 = *(const u32*)(Shi + r0 * STRA + k0 + tq);
        u32 ah1 = *(const u32*)(Shi + r1 * STRA + k0 + tq);
        u32 ah2 = *(const u32*)(Shi + r0 * STRA + k0 + tq + 8);
        u32 ah3 = *(const u32*)(Shi + r1 * STRA + k0 + tq + 8);
        u32 al0 = *(const u32*)(Slo + r0 * STRA + k0 + tq);
        u32 al1 = *(const u32*)(Slo + r1 * STRA + k0 + tq);
        u32 al2 = *(const u32*)(Slo + r0 * STRA + k0 + tq + 8);
        u32 al3 = *(const u32*)(Slo + r1 * STRA + k0 + tq + 8);
        #pragma unroll
        for (int nt = 0; nt < 8; nt++) {
            int fi = ((kt * 8 + nt) * 2) * 32 + lane;
            u32 bh0 = __ldg(&g_w2f_hi[fi]);
            u32 bh1 = __ldg(&g_w2f_hi[fi + 32]);
            u32 bl0 = __ldg(&g_w2f_lo[fi]);
            u32 bl1 = __ldg(&g_w2f_lo[fi + 32]);
            mma16816(acc2[nt], ah0, ah1, ah2, ah3, bh0, bh1);
            mma16816(acc2[nt], ah0, ah1, ah2, ah3, bl0, bl1);
            mma16816(acc2[nt], al0, al1, al2, al3, bh0, bh1);
        }
    }

    // ---- epilogue 2: out = D2 + b2 ----
    {
        int node0 = n0 + r0;
        int node1 = n0 + r1;
        #pragma unroll
        for (int nt = 0; nt < 8; nt++) {
            int d0 = 8 * nt + tq;
            float bA = __ldg(&b2[d0]);
            float bB = __ldg(&b2[d0 + 1]);
            if (node0 < N_NODES) {
                float2 v = make_float2(acc2[nt][0] + bA, acc2[nt][1] + bB);
                *reinterpret_cast<float2*>(out + (size_t)node0 * D + d0) = v;
            }
            if (node1 < N_NODES) {
                float2 v = make_float2(acc2[nt][2] + bA, acc2[nt][3] + bB);
                *reinterpret_cast<float2*>(out + (size_t)node1 * D + d0) = v;
            }
        }
    }
}

// ===========================================================================
extern "C" void kernel_launch(void* const* d_in, const int* in_sizes, int n_in,
                              void* d_out, int out_size) {
    const float* x  = (const float*)d_in[0];
    const int*   ei = (const int*)d_in[1];
    const float* W1 = (const float*)d_in[2];
    const float* b1 = (const float*)d_in[3];
    const float* W2 = (const float*)d_in[4];
    const float* b2 = (const float*)d_in[5];
    float* out = (float*)d_out;

    static void* cnt_ptr = nullptr;
    if (!cnt_ptr) cudaGetSymbolAddress(&cnt_ptr, g_cnt);
    cudaMemsetAsync(cnt_ptr, 0, N_NODES * sizeof(int));

    fill_kernel<<<(N_EDGES / 4 + 255) / 256, 256>>>(ei);

    split_w_kernel<<<32, 256>>>(W1, W2);

    gather_kernel<<<(N_NODES * 16 + 255) / 256, 256>>>(
        reinterpret_cast<const float4*>(x));

    {
        static bool attr_set = false;
        if (!attr_set) {
            cudaFuncSetAttribute(mlp_mma_kernel,
                                 cudaFuncAttributeMaxDynamicSharedMemorySize,
                                 SMEM_SZ);
            attr_set = true;
        }
        mlp_mma_kernel<<<(N_NODES + 127) / 128, 256, SMEM_SZ>>>(b1, b2, out);
    }
}

// round 16
// speedup vs baseline: 1.0252x; 1.0252x over previous
#include <cuda_runtime.h>
#include <cuda_bf16.h>
#include <cstdint>

#define N_NODES 100000
#define N_EDGES 1600000
#define D 64
#define H 128
#define CAP 64

#define STRA 72      // bf16 row stride for A/H tiles (36 words, conflict-free)

typedef uint32_t u32;

// ---- device scratch (no allocation allowed) ----
__device__ float g_agg[N_NODES * D];
__device__ int g_cnt[N_NODES];
__device__ int g_bucket[(size_t)N_NODES * CAP];
// packed fragment weights: one uint4 per (kt, nt, lane) = {bh0, bh1, bl0, bl1}
__device__ __align__(16) uint4 g_w1q[4 * 16 * 32];   // layer1: kt<4, nt<16
__device__ __align__(16) uint4 g_w2q[8 * 8 * 32];    // layer2: kt<8, nt<8

// ---- helpers ----
__device__ __forceinline__ void mma16816(float* c, u32 a0, u32 a1, u32 a2, u32 a3,
                                         u32 b0, u32 b1) {
    asm volatile(
        "mma.sync.aligned.m16n8k16.row.col.f32.bf16.bf16.f32 "
        "{%0,%1,%2,%3}, {%4,%5,%6,%7}, {%8,%9}, {%0,%1,%2,%3};"
        : "+f"(c[0]), "+f"(c[1]), "+f"(c[2]), "+f"(c[3])
        : "r"(a0), "r"(a1), "r"(a2), "r"(a3), "r"(b0), "r"(b1));
}

__device__ __forceinline__ void split2(float x0, float x1, u32& hi, u32& lo) {
    __nv_bfloat16 h0 = __float2bfloat16_rn(x0);
    __nv_bfloat16 h1 = __float2bfloat16_rn(x1);
    float r0 = x0 - __bfloat162float(h0);
    float r1 = x1 - __bfloat162float(h1);
    __nv_bfloat16 l0 = __float2bfloat16_rn(r0);
    __nv_bfloat16 l1 = __float2bfloat16_rn(r1);
    __nv_bfloat162 hp; hp.x = h0; hp.y = h1;
    __nv_bfloat162 lp; lp.x = l0; lp.y = l1;
    hi = *reinterpret_cast<u32*>(&hp);
    lo = *reinterpret_cast<u32*>(&lp);
}

// ===========================================================================
// Fill: 4 edges per thread
// ===========================================================================
__global__ void fill_kernel(const int* __restrict__ edge_index) {
    int gid = blockIdx.x * blockDim.x + threadIdx.x;
    if (gid >= N_EDGES / 4) return;
    int4 s4 = reinterpret_cast<const int4*>(edge_index)[gid];
    int4 d4 = reinterpret_cast<const int4*>(edge_index + N_EDGES)[gid];
    int p;
    p = atomicAdd(&g_cnt[d4.x], 1);
    if (p < CAP) g_bucket[(size_t)d4.x * CAP + p] = s4.x;
    p = atomicAdd(&g_cnt[d4.y], 1);
    if (p < CAP) g_bucket[(size_t)d4.y * CAP + p] = s4.y;
    p = atomicAdd(&g_cnt[d4.z], 1);
    if (p < CAP) g_bucket[(size_t)d4.z * CAP + p] = s4.z;
    p = atomicAdd(&g_cnt[d4.w], 1);
    if (p < CAP) g_bucket[(size_t)d4.w * CAP + p] = s4.w;
}

// ===========================================================================
// Gather: half-warp per node (unchanged)
// ===========================================================================
__global__ void __launch_bounds__(256) gather_kernel(const float4* __restrict__ x) {
    int hw = (blockIdx.x * 256 + threadIdx.x) >> 4;
    if (hw >= N_NODES) return;
    int q = threadIdx.x & 15;

    const int* bkt = g_bucket + (size_t)hw * CAP;
    int deg = g_cnt[hw];
    if (deg > CAP) deg = CAP;

    float4 acc = __ldg(&x[(size_t)hw * 16 + q]);
    float4 acc2 = make_float4(0.f, 0.f, 0.f, 0.f);

    int i = 0;
    for (; i + 1 < deg; i += 2) {
        int s0 = __ldg(&bkt[i]);
        int s1 = __ldg(&bkt[i + 1]);
        float4 v0 = __ldg(&x[(size_t)s0 * 16 + q]);
        float4 v1 = __ldg(&x[(size_t)s1 * 16 + q]);
        acc.x += v0.x;  acc.y += v0.y;  acc.z += v0.z;  acc.w += v0.w;
        acc2.x += v1.x; acc2.y += v1.y; acc2.z += v1.z; acc2.w += v1.w;
    }
    if (i < deg) {
        int s0 = __ldg(&bkt[i]);
        float4 v0 = __ldg(&x[(size_t)s0 * 16 + q]);
        acc.x += v0.x; acc.y += v0.y; acc.z += v0.z; acc.w += v0.w;
    }
    acc.x += acc2.x; acc.y += acc2.y; acc.z += acc2.z; acc.w += acc2.w;

    reinterpret_cast<float4*>(g_agg)[(size_t)hw * 16 + q] = acc;
}

// ===========================================================================
// One-time weight split into packed uint4 fragments.
// W1: i in [0,2048): lane=i&31, nt=(i>>5)&15, kt=i>>9
//   j = nt*8 + (lane>>2); k = kt*16 + (lane&3)*2
//   frag = { bf16x2(W1T[j][k..k+1])hi, bf16x2(W1T[j][k+8..k+9])hi,
//            ...same lo }                     W1T[j][k] = W1[k*H+j]
// W2: i in [0,2048): lane=i&31, nt=(i>>5)&7, kt=i>>8
//   d = nt*8 + (lane>>2); j = kt*16 + (lane&3)*2
//   values W2T[d][j] = W2[j*D+d]
// ===========================================================================
__global__ void split_w_kernel(const float* __restrict__ W1,
                               const float* __restrict__ W2) {
    int i = blockIdx.x * blockDim.x + threadIdx.x;
    if (i < 2048) {                                   // W1 frags
        int lane = i & 31;
        int nt = (i >> 5) & 15;
        int kt = i >> 9;
        int j = nt * 8 + (lane >> 2);
        int k = kt * 16 + (lane & 3) * 2;
        u32 bh0, bl0, bh1, bl1;
        split2(W1[k * H + j],       W1[(k + 1) * H + j], bh0, bl0);
        split2(W1[(k + 8) * H + j], W1[(k + 9) * H + j], bh1, bl1);
        uint4 v; v.x = bh0; v.y = bh1; v.z = bl0; v.w = bl1;
        g_w1q[i] = v;
    } else if (i < 4096) {                            // W2 frags
        int p = i - 2048;
        int lane = p & 31;
        int nt = (p >> 5) & 7;
        int kt = p >> 8;
        int d = nt * 8 + (lane >> 2);
        int j = kt * 16 + (lane & 3) * 2;
        u32 bh0, bl0, bh1, bl1;
        split2(W2[j * D + d],       W2[(j + 1) * D + d], bh0, bl0);
        split2(W2[(j + 8) * D + d], W2[(j + 9) * D + d], bh1, bl1);
        uint4 v; v.x = bh0; v.y = bh1; v.z = bl0; v.w = bl1;
        g_w2q[p] = v;
    }
}

// ===========================================================================
// Warp-autonomous mma.sync MLP (R15 structure), weights via packed LDG.128.
// ===========================================================================
#define OFF_AHI   0
#define OFF_ALO   18432
#define OFF_HAHI  36864
#define OFF_HALO  55296
#define SMEM_SZ   73728

__global__ void __launch_bounds__(256, 3) mlp_mma_kernel(
    const float* __restrict__ b1, const float* __restrict__ b2,
    float* __restrict__ out)
{
    extern __shared__ unsigned char sm[];
    __nv_bfloat16* Ahi  = (__nv_bfloat16*)(sm + OFF_AHI);
    __nv_bfloat16* Alo  = (__nv_bfloat16*)(sm + OFF_ALO);
    __nv_bfloat16* HAhi = (__nv_bfloat16*)(sm + OFF_HAHI);
    __nv_bfloat16* HAlo = (__nv_bfloat16*)(sm + OFF_HALO);
    __nv_bfloat16* HBhi = Ahi;     // overlay after A consumed (warp-local)
    __nv_bfloat16* HBlo = Alo;

    const int t    = threadIdx.x;
    const int w    = t >> 5;
    const int lane = t & 31;
    const int g    = lane >> 2;
    const int tq   = (lane & 3) * 2;
    const int n0   = blockIdx.x * 128;

    // ---- stage A (warp-local rows) ----
    {
        int n = t >> 1, half = t & 1;
        int node = n0 + n;
        const float4* ap = reinterpret_cast<const float4*>(g_agg)
                           + (size_t)node * 16 + half * 8;
        #pragma unroll
        for (int q = 0; q < 8; q++) {
            float4 v = (node < N_NODES) ? __ldg(&ap[q])
                                        : make_float4(0.f, 0.f, 0.f, 0.f);
            int k = half * 32 + 4 * q;
            u32 h0, l0, h1, l1;
            split2(v.x, v.y, h0, l0);
            split2(v.z, v.w, h1, l1);
            *(u32*)(Ahi + n * STRA + k)     = h0;
            *(u32*)(Ahi + n * STRA + k + 2) = h1;
            *(u32*)(Alo + n * STRA + k)     = l0;
            *(u32*)(Alo + n * STRA + k + 2) = l1;
        }
    }
    __syncwarp();

    const int r0 = 16 * w + g;
    const int r1 = r0 + 8;

    // ---- layer 1: two j-passes ----
    #pragma unroll
    for (int p = 0; p < 2; p++) {
        float acc[8][4];
        #pragma unroll
        for (int nt = 0; nt < 8; nt++)
            #pragma unroll
            for (int i = 0; i < 4; i++) acc[nt][i] = 0.f;

        const __nv_bfloat16* A0h = Ahi + r0 * STRA;
        const __nv_bfloat16* A1h = Ahi + r1 * STRA;
        const __nv_bfloat16* A0l = Alo + r0 * STRA;
        const __nv_bfloat16* A1l = Alo + r1 * STRA;
        #pragma unroll
        for (int kt = 0; kt < 4; kt++) {
            int k0 = kt * 16;
            u32 ah0 = *(const u32*)(A0h + k0 + tq);
            u32 ah1 = *(const u32*)(A1h + k0 + tq);
            u32 ah2 = *(const u32*)(A0h + k0 + tq + 8);
            u32 ah3 = *(const u32*)(A1h + k0 + tq + 8);
            u32 al0 = *(const u32*)(A0l + k0 + tq);
            u32 al1 = *(const u32*)(A1l + k0 + tq);
            u32 al2 = *(const u32*)(A0l + k0 + tq + 8);
            u32 al3 = *(const u32*)(A1l + k0 + tq + 8);
            #pragma unroll
            for (int nt2 = 0; nt2 < 8; nt2++) {
                int nt = p * 8 + nt2;
                uint4 wv = __ldg(&g_w1q[(kt * 16 + nt) * 32 + lane]);
                mma16816(acc[nt2], ah0, ah1, ah2, ah3, wv.x, wv.y);  // hi*hi
                mma16816(acc[nt2], ah0, ah1, ah2, ah3, wv.z, wv.w);  // hi*lo
                mma16816(acc[nt2], al0, al1, al2, al3, wv.x, wv.y);  // lo*hi
            }
        }

        // epilogue: relu + bias, split, write H half (warp-local rows)
        __nv_bfloat16* Dhi = p ? HBhi : HAhi;
        __nv_bfloat16* Dlo = p ? HBlo : HAlo;
        __syncwarp();
        #pragma unroll
        for (int nt2 = 0; nt2 < 8; nt2++) {
            int j0 = p * 64 + 8 * nt2 + tq;
            int c0 = 8 * nt2 + tq;
            float bA = __ldg(&b1[j0]);
            float bB = __ldg(&b1[j0 + 1]);
            float h00 = fmaxf(acc[nt2][0] + bA, 0.f);
            float h01 = fmaxf(acc[nt2][1] + bB, 0.f);
            float h10 = fmaxf(acc[nt2][2] + bA, 0.f);
            float h11 = fmaxf(acc[nt2][3] + bB, 0.f);
            u32 hi, lo;
            split2(h00, h01, hi, lo);
            *(u32*)(Dhi + r0 * STRA + c0) = hi;
            *(u32*)(Dlo + r0 * STRA + c0) = lo;
            split2(h10, h11, hi, lo);
            *(u32*)(Dhi + r1 * STRA + c0) = hi;
            *(u32*)(Dlo + r1 * STRA + c0) = lo;
        }
        __syncwarp();
    }

    // ---- layer 2: K=128 ----
    float acc2[8][4];
    #pragma unroll
    for (int nt = 0; nt < 8; nt++)
        #pragma unroll
        for (int i = 0; i < 4; i++) acc2[nt][i] = 0.f;

    #pragma unroll
    for (int kt = 0; kt < 8; kt++) {
        const __nv_bfloat16* Shi = (kt < 4) ? HAhi : HBhi;
        const __nv_bfloat16* Slo = (kt < 4) ? HAlo : HBlo;
        int k0 = (kt & 3) * 16;
        u32 ah0 = *(const u32*)(Shi + r0 * STRA + k0 + tq);
        u32 ah1 = *(const u32*)(Shi + r1 * STRA + k0 + tq);
        u32 ah2 = *(const u32*)(Shi + r0 * STRA + k0 + tq + 8);
        u32 ah3 = *(const u32*)(Shi + r1 * STRA + k0 + tq + 8);
        u32 al0 = *(const u32*)(Slo + r0 * STRA + k0 + tq);
        u32 al1 = *(const u32*)(Slo + r1 * STRA + k0 + tq);
        u32 al2 = *(const u32*)(Slo + r0 * STRA + k0 + tq + 8);
        u32 al3 = *(const u32*)(Slo + r1 * STRA + k0 + tq + 8);
        #pragma unroll
        for (int nt = 0; nt < 8; nt++) {
            uint4 wv = __ldg(&g_w2q[(kt * 8 + nt) * 32 + lane]);
            mma16816(acc2[nt], ah0, ah1, ah2, ah3, wv.x, wv.y);
            mma16816(acc2[nt], ah0, ah1, ah2, ah3, wv.z, wv.w);
            mma16816(acc2[nt], al0, al1, al2, al3, wv.x, wv.y);
        }
    }

    // ---- epilogue 2 ----
    {
        int node0 = n0 + r0;
        int node1 = n0 + r1;
        #pragma unroll
        for (int nt = 0; nt < 8; nt++) {
            int d0 = 8 * nt + tq;
            float bA = __ldg(&b2[d0]);
            float bB = __ldg(&b2[d0 + 1]);
            if (node0 < N_NODES) {
                float2 v = make_float2(acc2[nt][0] + bA, acc2[nt][1] + bB);
                *reinterpret_cast<float2*>(out + (size_t)node0 * D + d0) = v;
            }
            if (node1 < N_NODES) {
                float2 v = make_float2(acc2[nt][2] + bA, acc2[nt][3] + bB);
                *reinterpret_cast<float2*>(out + (size_t)node1 * D + d0) = v;
            }
        }
    }
}

// ===========================================================================
extern "C" void kernel_launch(void* const* d_in, const int* in_sizes, int n_in,
                              void* d_out, int out_size) {
    const float* x  = (const float*)d_in[0];
    const int*   ei = (const int*)d_in[1];
    const float* W1 = (const float*)d_in[2];
    const float* b1 = (const float*)d_in[3];
    const float* W2 = (const float*)d_in[4];
    const float* b2 = (const float*)d_in[5];
    float* out = (float*)d_out;

    static void* cnt_ptr = nullptr;
    if (!cnt_ptr) cudaGetSymbolAddress(&cnt_ptr, g_cnt);
    cudaMemsetAsync(cnt_ptr, 0, N_NODES * sizeof(int));

    fill_kernel<<<(N_EDGES / 4 + 255) / 256, 256>>>(ei);

    split_w_kernel<<<16, 256>>>(W1, W2);

    gather_kernel<<<(N_NODES * 16 + 255) / 256, 256>>>(
        reinterpret_cast<const float4*>(x));

    {
        static bool attr_set = false;
        if (!attr_set) {
            cudaFuncSetAttribute(mlp_mma_kernel,
                                 cudaFuncAttributeMaxDynamicSharedMemorySize,
                                 SMEM_SZ);
            attr_set = true;
        }
        mlp_mma_kernel<<<(N_NODES + 127) / 128, 256, SMEM_SZ>>>(b1, b2, out);
    }
}

// round 17
// speedup vs baseline: 1.1113x; 1.0839x over previous
#include <cuda_runtime.h>
#include <cuda_bf16.h>
#include <cstdint>

#define N_NODES 100000
#define N_EDGES 1600000
#define D 64
#define H 128
#define CAP 64

#define STRA 72      // bf16 row stride for A/H tiles (36 words, conflict-free)

typedef uint32_t u32;

// ---- device scratch (no allocation allowed) ----
__device__ float g_agg[N_NODES * D];
__device__ int g_cnt[N_NODES];
__device__ int g_bucket[(size_t)N_NODES * CAP];
// packed fragment weights: one uint4 per (kt, nt, lane) = {bh0, bh1, bl0, bl1}
__device__ __align__(16) uint4 g_w1q[4 * 16 * 32];   // layer1: kt<4, nt<16
__device__ __align__(16) uint4 g_w2q[8 * 8 * 32];    // layer2: kt<8, nt<8

// ---- helpers ----
__device__ __forceinline__ void mma16816(float* c, u32 a0, u32 a1, u32 a2, u32 a3,
                                         u32 b0, u32 b1) {
    asm volatile(
        "mma.sync.aligned.m16n8k16.row.col.f32.bf16.bf16.f32 "
        "{%0,%1,%2,%3}, {%4,%5,%6,%7}, {%8,%9}, {%0,%1,%2,%3};"
        : "+f"(c[0]), "+f"(c[1]), "+f"(c[2]), "+f"(c[3])
        : "r"(a0), "r"(a1), "r"(a2), "r"(a3), "r"(b0), "r"(b1));
}

__device__ __forceinline__ void split2(float x0, float x1, u32& hi, u32& lo) {
    __nv_bfloat16 h0 = __float2bfloat16_rn(x0);
    __nv_bfloat16 h1 = __float2bfloat16_rn(x1);
    float r0 = x0 - __bfloat162float(h0);
    float r1 = x1 - __bfloat162float(h1);
    __nv_bfloat16 l0 = __float2bfloat16_rn(r0);
    __nv_bfloat16 l1 = __float2bfloat16_rn(r1);
    __nv_bfloat162 hp; hp.x = h0; hp.y = h1;
    __nv_bfloat162 lp; lp.x = l0; lp.y = l1;
    hi = *reinterpret_cast<u32*>(&hp);
    lo = *reinterpret_cast<u32*>(&lp);
}

// ===========================================================================
// Fill: 4 edges per thread (unchanged)
// ===========================================================================
__global__ void fill_kernel(const int* __restrict__ edge_index) {
    int gid = blockIdx.x * blockDim.x + threadIdx.x;
    if (gid >= N_EDGES / 4) return;
    int4 s4 = reinterpret_cast<const int4*>(edge_index)[gid];
    int4 d4 = reinterpret_cast<const int4*>(edge_index + N_EDGES)[gid];
    int p;
    p = atomicAdd(&g_cnt[d4.x], 1);
    if (p < CAP) g_bucket[(size_t)d4.x * CAP + p] = s4.x;
    p = atomicAdd(&g_cnt[d4.y], 1);
    if (p < CAP) g_bucket[(size_t)d4.y * CAP + p] = s4.y;
    p = atomicAdd(&g_cnt[d4.z], 1);
    if (p < CAP) g_bucket[(size_t)d4.z * CAP + p] = s4.z;
    p = atomicAdd(&g_cnt[d4.w], 1);
    if (p < CAP) g_bucket[(size_t)d4.w * CAP + p] = s4.w;
}

// ===========================================================================
// Gather: half-warp per node (unchanged)
// ===========================================================================
__global__ void __launch_bounds__(256) gather_kernel(const float4* __restrict__ x) {
    int hw = (blockIdx.x * 256 + threadIdx.x) >> 4;
    if (hw >= N_NODES) return;
    int q = threadIdx.x & 15;

    const int* bkt = g_bucket + (size_t)hw * CAP;
    int deg = g_cnt[hw];
    if (deg > CAP) deg = CAP;

    float4 acc = __ldg(&x[(size_t)hw * 16 + q]);
    float4 acc2 = make_float4(0.f, 0.f, 0.f, 0.f);

    int i = 0;
    for (; i + 1 < deg; i += 2) {
        int s0 = __ldg(&bkt[i]);
        int s1 = __ldg(&bkt[i + 1]);
        float4 v0 = __ldg(&x[(size_t)s0 * 16 + q]);
        float4 v1 = __ldg(&x[(size_t)s1 * 16 + q]);
        acc.x += v0.x;  acc.y += v0.y;  acc.z += v0.z;  acc.w += v0.w;
        acc2.x += v1.x; acc2.y += v1.y; acc2.z += v1.z; acc2.w += v1.w;
    }
    if (i < deg) {
        int s0 = __ldg(&bkt[i]);
        float4 v0 = __ldg(&x[(size_t)s0 * 16 + q]);
        acc.x += v0.x; acc.y += v0.y; acc.z += v0.z; acc.w += v0.w;
    }
    acc.x += acc2.x; acc.y += acc2.y; acc.z += acc2.z; acc.w += acc2.w;

    reinterpret_cast<float4*>(g_agg)[(size_t)hw * 16 + q] = acc;
}

// ===========================================================================
// One-time weight split into packed uint4 fragments (unchanged layout)
// ===========================================================================
__global__ void split_w_kernel(const float* __restrict__ W1,
                               const float* __restrict__ W2) {
    int i = blockIdx.x * blockDim.x + threadIdx.x;
    if (i < 2048) {                                   // W1 frags
        int lane = i & 31;
        int nt = (i >> 5) & 15;
        int kt = i >> 9;
        int j = nt * 8 + (lane >> 2);
        int k = kt * 16 + (lane & 3) * 2;
        u32 bh0, bl0, bh1, bl1;
        split2(W1[k * H + j],       W1[(k + 1) * H + j], bh0, bl0);
        split2(W1[(k + 8) * H + j], W1[(k + 9) * H + j], bh1, bl1);
        uint4 v; v.x = bh0; v.y = bh1; v.z = bl0; v.w = bl1;
        g_w1q[i] = v;
    } else if (i < 4096) {                            // W2 frags
        int p = i - 2048;
        int lane = p & 31;
        int nt = (p >> 5) & 7;
        int kt = p >> 8;
        int d = nt * 8 + (lane >> 2);
        int j = kt * 16 + (lane & 3) * 2;
        u32 bh0, bl0, bh1, bl1;
        split2(W2[j * D + d],       W2[(j + 1) * D + d], bh0, bl0);
        split2(W2[(j + 8) * D + d], W2[(j + 9) * D + d], bh1, bl1);
        uint4 v; v.x = bh0; v.y = bh1; v.z = bl0; v.w = bl1;
        g_w2q[p] = v;
    }
}

// ===========================================================================
// Warp-autonomous mma.sync MLP: 128 nodes/block, 128 threads (4 warps).
// Warp w owns 32 rows = two m16 tiles (rows 32w..32w+15, 32w+16..32w+31);
// 6 MMAs per weight uint4 -> weight L1 traffic halved vs R16.
// ===========================================================================
#define OFF_AHI   0
#define OFF_ALO   18432
#define OFF_HAHI  36864
#define OFF_HALO  55296
#define SMEM_SZ   73728

__global__ void __launch_bounds__(128, 3) mlp_mma_kernel(
    const float* __restrict__ b1, const float* __restrict__ b2,
    float* __restrict__ out)
{
    extern __shared__ unsigned char sm[];
    __nv_bfloat16* Ahi  = (__nv_bfloat16*)(sm + OFF_AHI);
    __nv_bfloat16* Alo  = (__nv_bfloat16*)(sm + OFF_ALO);
    __nv_bfloat16* HAhi = (__nv_bfloat16*)(sm + OFF_HAHI);
    __nv_bfloat16* HAlo = (__nv_bfloat16*)(sm + OFF_HALO);
    __nv_bfloat16* HBhi = Ahi;     // overlay after A consumed (warp-local)
    __nv_bfloat16* HBlo = Alo;

    const int t    = threadIdx.x;
    const int w    = t >> 5;
    const int lane = t & 31;
    const int g    = lane >> 2;
    const int tq   = (lane & 3) * 2;
    const int n0   = blockIdx.x * 128;

    // ---- stage A: thread t owns full row t (warp-local rows 32w..32w+31) ----
    {
        int node = n0 + t;
        const float4* ap = reinterpret_cast<const float4*>(g_agg)
                           + (size_t)node * 16;
        #pragma unroll
        for (int q = 0; q < 16; q++) {
            float4 v = (node < N_NODES) ? __ldg(&ap[q])
                                        : make_float4(0.f, 0.f, 0.f, 0.f);
            int k = 4 * q;
            u32 h0, l0, h1, l1;
            split2(v.x, v.y, h0, l0);
            split2(v.z, v.w, h1, l1);
            *(u32*)(Ahi + t * STRA + k)     = h0;
            *(u32*)(Ahi + t * STRA + k + 2) = h1;
            *(u32*)(Alo + t * STRA + k)     = l0;
            *(u32*)(Alo + t * STRA + k + 2) = l1;
        }
    }
    __syncwarp();

    // warp row bases: tile0 = rows r0,r1 ; tile1 = rows r2,r3
    const int r0 = 32 * w + g;
    const int r1 = r0 + 8;
    const int r2 = r0 + 16;
    const int r3 = r0 + 24;

    // ---- layer 1: two j-passes (pass p covers j in [64p, 64p+64)) ----
    #pragma unroll
    for (int p = 0; p < 2; p++) {
        float acc[8][2][4];
        #pragma unroll
        for (int nt = 0; nt < 8; nt++)
            #pragma unroll
            for (int tl = 0; tl < 2; tl++)
                #pragma unroll
                for (int i = 0; i < 4; i++) acc[nt][tl][i] = 0.f;

        #pragma unroll
        for (int kt = 0; kt < 4; kt++) {
            int k0 = kt * 16;
            // tile 0 frags
            u32 xh0 = *(const u32*)(Ahi + r0 * STRA + k0 + tq);
            u32 xh1 = *(const u32*)(Ahi + r1 * STRA + k0 + tq);
            u32 xh2 = *(const u32*)(Ahi + r0 * STRA + k0 + tq + 8);
            u32 xh3 = *(const u32*)(Ahi + r1 * STRA + k0 + tq + 8);
            u32 xl0 = *(const u32*)(Alo + r0 * STRA + k0 + tq);
            u32 xl1 = *(const u32*)(Alo + r1 * STRA + k0 + tq);
            u32 xl2 = *(const u32*)(Alo + r0 * STRA + k0 + tq + 8);
            u32 xl3 = *(const u32*)(Alo + r1 * STRA + k0 + tq + 8);
            // tile 1 frags
            u32 yh0 = *(const u32*)(Ahi + r2 * STRA + k0 + tq);
            u32 yh1 = *(const u32*)(Ahi + r3 * STRA + k0 + tq);
            u32 yh2 = *(const u32*)(Ahi + r2 * STRA + k0 + tq + 8);
            u32 yh3 = *(const u32*)(Ahi + r3 * STRA + k0 + tq + 8);
            u32 yl0 = *(const u32*)(Alo + r2 * STRA + k0 + tq);
            u32 yl1 = *(const u32*)(Alo + r3 * STRA + k0 + tq);
            u32 yl2 = *(const u32*)(Alo + r2 * STRA + k0 + tq + 8);
            u32 yl3 = *(const u32*)(Alo + r3 * STRA + k0 + tq + 8);
            #pragma unroll
            for (int nt2 = 0; nt2 < 8; nt2++) {
                int nt = p * 8 + nt2;
                uint4 wv = __ldg(&g_w1q[(kt * 16 + nt) * 32 + lane]);
                mma16816(acc[nt2][0], xh0, xh1, xh2, xh3, wv.x, wv.y);
                mma16816(acc[nt2][0], xh0, xh1, xh2, xh3, wv.z, wv.w);
                mma16816(acc[nt2][0], xl0, xl1, xl2, xl3, wv.x, wv.y);
                mma16816(acc[nt2][1], yh0, yh1, yh2, yh3, wv.x, wv.y);
                mma16816(acc[nt2][1], yh0, yh1, yh2, yh3, wv.z, wv.w);
                mma16816(acc[nt2][1], yl0, yl1, yl2, yl3, wv.x, wv.y);
            }
        }

        // epilogue: relu + bias, split, write H half (warp-local rows)
        __nv_bfloat16* Dhi = p ? HBhi : HAhi;
        __nv_bfloat16* Dlo = p ? HBlo : HAlo;
        __syncwarp();
        #pragma unroll
        for (int nt2 = 0; nt2 < 8; nt2++) {
            int j0 = p * 64 + 8 * nt2 + tq;
            int c0 = 8 * nt2 + tq;
            float bA = __ldg(&b1[j0]);
            float bB = __ldg(&b1[j0 + 1]);
            #pragma unroll
            for (int tl = 0; tl < 2; tl++) {
                int ra = tl ? r2 : r0;
                int rb = tl ? r3 : r1;
                float h00 = fmaxf(acc[nt2][tl][0] + bA, 0.f);
                float h01 = fmaxf(acc[nt2][tl][1] + bB, 0.f);
                float h10 = fmaxf(acc[nt2][tl][2] + bA, 0.f);
                float h11 = fmaxf(acc[nt2][tl][3] + bB, 0.f);
                u32 hi, lo;
                split2(h00, h01, hi, lo);
                *(u32*)(Dhi + ra * STRA + c0) = hi;
                *(u32*)(Dlo + ra * STRA + c0) = lo;
                split2(h10, h11, hi, lo);
                *(u32*)(Dhi + rb * STRA + c0) = hi;
                *(u32*)(Dlo + rb * STRA + c0) = lo;
            }
        }
        __syncwarp();
    }

    // ---- layer 2: K=128 (kt<4 from H_A, kt>=4 from H_B) ----
    float acc2[8][2][4];
    #pragma unroll
    for (int nt = 0; nt < 8; nt++)
        #pragma unroll
        for (int tl = 0; tl < 2; tl++)
            #pragma unroll
            for (int i = 0; i < 4; i++) acc2[nt][tl][i] = 0.f;

    #pragma unroll
    for (int kt = 0; kt < 8; kt++) {
        const __nv_bfloat16* Shi = (kt < 4) ? HAhi : HBhi;
        const __nv_bfloat16* Slo = (kt < 4) ? HAlo : HBlo;
        int k0 = (kt & 3) * 16;
        u32 xh0 = *(const u32*)(Shi + r0 * STRA + k0 + tq);
        u32 xh1 = *(const u32*)(Shi + r1 * STRA + k0 + tq);
        u32 xh2 = *(const u32*)(Shi + r0 * STRA + k0 + tq + 8);
        u32 xh3 = *(const u32*)(Shi + r1 * STRA + k0 + tq + 8);
        u32 xl0 = *(const u32*)(Slo + r0 * STRA + k0 + tq);
        u32 xl1 = *(const u32*)(Slo + r1 * STRA + k0 + tq);
        u32 xl2 = *(const u32*)(Slo + r0 * STRA + k0 + tq + 8);
        u32 xl3 = *(const u32*)(Slo + r1 * STRA + k0 + tq + 8);
        u32 yh0 = *(const u32*)(Shi + r2 * STRA + k0 + tq);
        u32 yh1 = *(const u32*)(Shi + r3 * STRA + k0 + tq);
        u32 yh2 = *(const u32*)(Shi + r2 * STRA + k0 + tq + 8);
        u32 yh3 = *(const u32*)(Shi + r3 * STRA + k0 + tq + 8);
        u32 yl0 = *(const u32*)(Slo + r2 * STRA + k0 + tq);
        u32 yl1 = *(const u32*)(Slo + r3 * STRA + k0 + tq);
        u32 yl2 = *(const u32*)(Slo + r2 * STRA + k0 + tq + 8);
        u32 yl3 = *(const u32*)(Slo + r3 * STRA + k0 + tq + 8);
        #pragma unroll
        for (int nt = 0; nt < 8; nt++) {
            uint4 wv = __ldg(&g_w2q[(kt * 8 + nt) * 32 + lane]);
            mma16816(acc2[nt][0], xh0, xh1, xh2, xh3, wv.x, wv.y);
            mma16816(acc2[nt][0], xh0, xh1, xh2, xh3, wv.z, wv.w);
            mma16816(acc2[nt][0], xl0, xl1, xl2, xl3, wv.x, wv.y);
            mma16816(acc2[nt][1], yh0, yh1, yh2, yh3, wv.x, wv.y);
            mma16816(acc2[nt][1], yh0, yh1, yh2, yh3, wv.z, wv.w);
            mma16816(acc2[nt][1], yl0, yl1, yl2, yl3, wv.x, wv.y);
        }
    }

    // ---- epilogue 2: out = D2 + b2 ----
    {
        #pragma unroll
        for (int nt = 0; nt < 8; nt++) {
            int d0 = 8 * nt + tq;
            float bA = __ldg(&b2[d0]);
            float bB = __ldg(&b2[d0 + 1]);
            #pragma unroll
            for (int tl = 0; tl < 2; tl++) {
                int nodeA = n0 + (tl ? r2 : r0);
                int nodeB = n0 + (tl ? r3 : r1);
                if (nodeA < N_NODES) {
                    float2 v = make_float2(acc2[nt][tl][0] + bA,
                                           acc2[nt][tl][1] + bB);
                    *reinterpret_cast<float2*>(out + (size_t)nodeA * D + d0) = v;
                }
                if (nodeB < N_NODES) {
                    float2 v = make_float2(acc2[nt][tl][2] + bA,
                                           acc2[nt][tl][3] + bB);
                    *reinterpret_cast<float2*>(out + (size_t)nodeB * D + d0) = v;
                }
            }
        }
    }
}

// ===========================================================================
extern "C" void kernel_launch(void* const* d_in, const int* in_sizes, int n_in,
                              void* d_out, int out_size) {
    const float* x  = (const float*)d_in[0];
    const int*   ei = (const int*)d_in[1];
    const float* W1 = (const float*)d_in[2];
    const float* b1 = (const float*)d_in[3];
    const float* W2 = (const float*)d_in[4];
    const float* b2 = (const float*)d_in[5];
    float* out = (float*)d_out;

    static void* cnt_ptr = nullptr;
    if (!cnt_ptr) cudaGetSymbolAddress(&cnt_ptr, g_cnt);
    cudaMemsetAsync(cnt_ptr, 0, N_NODES * sizeof(int));

    fill_kernel<<<(N_EDGES / 4 + 255) / 256, 256>>>(ei);

    split_w_kernel<<<16, 256>>>(W1, W2);

    gather_kernel<<<(N_NODES * 16 + 255) / 256, 256>>>(
        reinterpret_cast<const float4*>(x));

    {
        static bool attr_set = false;
        if (!attr_set) {
            cudaFuncSetAttribute(mlp_mma_kernel,
                                 cudaFuncAttributeMaxDynamicSharedMemorySize,
                                 SMEM_SZ);
            attr_set = true;
        }
        mlp_mma_kernel<<<(N_NODES + 127) / 128, 128, SMEM_SZ>>>(b1, b2, out);
    }
}